// round 11
// baseline (speedup 1.0000x reference)
#include <cuda_runtime.h>
#include <cuda_bf16.h>
#include <cuda_fp16.h>
#include <math.h>
#include <stdint.h>

// ---------------------------------------------------------------------------
// Problem constants
// ---------------------------------------------------------------------------
#define B_   2
#define T_   2048
#define D_   1024
#define NH_  16
#define DH_  64
#define FFN_ 2736
#define FFNP 2816
#define M_   (B_ * T_)
#define EPS_ 1e-6f

// ---------------------------------------------------------------------------
// PTX helpers (arch-generic, sm_80+)
// ---------------------------------------------------------------------------
__device__ __forceinline__ uint32_t smem_u32(const void* p) {
    uint32_t a;
    asm("{ .reg .u64 t; cvta.to.shared.u64 t, %1; cvt.u32.u64 %0, t; }"
        : "=r"(a) : "l"(p));
    return a;
}
#define CP_ASYNC16(dst, src) \
    asm volatile("cp.async.cg.shared.global [%0], [%1], 16;" :: "r"(dst), "l"(src))
#define CP_COMMIT() asm volatile("cp.async.commit_group;" ::: "memory")
#define CP_WAIT0()  asm volatile("cp.async.wait_group 0;" ::: "memory")
#define CP_WAIT1()  asm volatile("cp.async.wait_group 1;" ::: "memory")
#define LDSM_X4(r0, r1, r2, r3, addr) \
    asm volatile("ldmatrix.sync.aligned.m8n8.x4.shared.b16 {%0,%1,%2,%3}, [%4];" \
                 : "=r"(r0), "=r"(r1), "=r"(r2), "=r"(r3) : "r"(addr))
#define MMA16816(d, a, b0, b1) \
    asm volatile("mma.sync.aligned.m16n8k16.row.col.f32.bf16.bf16.f32 " \
                 "{%0,%1,%2,%3},{%4,%5,%6,%7},{%8,%9},{%0,%1,%2,%3};" \
                 : "+f"((d)[0]), "+f"((d)[1]), "+f"((d)[2]), "+f"((d)[3]) \
                 : "r"((a)[0]), "r"((a)[1]), "r"((a)[2]), "r"((a)[3]), \
                   "r"(b0), "r"(b1))
#define MMAH16816(d, a, b0, b1) \
    asm volatile("mma.sync.aligned.m16n8k16.row.col.f32.f16.f16.f32 " \
                 "{%0,%1,%2,%3},{%4,%5,%6,%7},{%8,%9},{%0,%1,%2,%3};" \
                 : "+f"((d)[0]), "+f"((d)[1]), "+f"((d)[2]), "+f"((d)[3]) \
                 : "r"((a)[0]), "r"((a)[1]), "r"((a)[2]), "r"((a)[3]), \
                   "r"(b0), "r"(b1))
__device__ __forceinline__ uint32_t h2bits(float a, float b) {
    __half2 t = __floats2half2_rn(a, b);
    return *(uint32_t*)&t;
}

// ---------------------------------------------------------------------------
// Device scratch
// ---------------------------------------------------------------------------
__device__ float s_xmix[M_ * D_];
__device__ float s_dd  [M_ * NH_ * 16];
__device__ float s_csum[B_ * 16 * 256];
__device__ float s_x2  [M_ * D_];
__device__ __half s_qkvh[(size_t)M_ * 3 * D_];
__device__ __half s_qth [B_ * NH_ * T_ * DH_];
__device__ __half s_kth [B_ * NH_ * T_ * DH_];
__device__ __half s_vth [B_ * NH_ * T_ * DH_];
__device__ __half s_guh [(size_t)M_ * FFNP];          // fused act output
// bf16 split buffers (dd path only)
__device__ __nv_bfloat16 g_ah[(size_t)M_ * D_];
__device__ __nv_bfloat16 g_al[(size_t)M_ * D_];
__device__ __nv_bfloat16 g_wh[256 * D_];
__device__ __nv_bfloat16 g_wl[256 * D_];
// fp16 buffers (main GEMM path)
__device__ __half g_af[(size_t)M_ * FFNP];
__device__ __half g_wf[(size_t)2 * FFNP * D_];

// ---------------------------------------------------------------------------
// conversions
// ---------------------------------------------------------------------------
__global__ void convsplit(const float* __restrict__ src,
                          __nv_bfloat16* __restrict__ h,
                          __nv_bfloat16* __restrict__ l,
                          int rows, int cols, int rows_pad, int cols_pad)
{
    size_t i = (size_t)blockIdx.x * blockDim.x + threadIdx.x;
    size_t total = (size_t)rows_pad * cols_pad;
    if (i >= total) return;
    int r = (int)(i / cols_pad);
    int c = (int)(i - (size_t)r * cols_pad);
    float v = (r < rows && c < cols) ? src[(size_t)r * cols + c] : 0.f;
    __nv_bfloat16 hi = __float2bfloat16(v);
    h[i] = hi;
    l[i] = __float2bfloat16(v - __bfloat162float(hi));
}

__global__ void conv_whalf(const float* __restrict__ src,
                           __half* __restrict__ d,
                           int rows, int cols, int rows_pad, int cols_pad)
{
    size_t i = (size_t)blockIdx.x * blockDim.x + threadIdx.x;
    size_t total = (size_t)rows_pad * cols_pad;
    if (i >= total) return;
    int r = (int)(i / cols_pad);
    int c = (int)(i - (size_t)r * cols_pad);
    float v = (r < rows && c < cols) ? src[(size_t)r * cols + c] : 0.f;
    d[i] = __float2half(v);
}

// interleave gate/up rows: out row 2i <- gate row i, 2i+1 <- up row i
__global__ void conv_wgu(const float* __restrict__ gw,
                         const float* __restrict__ uw,
                         __half* __restrict__ d)
{
    size_t i = (size_t)blockIdx.x * blockDim.x + threadIdx.x;  // over 2*FFNP*D
    if (i >= (size_t)2 * FFNP * D_) return;
    int r = (int)(i / D_);
    int c = (int)(i - (size_t)r * D_);
    int srow = r >> 1;
    const float* src = (r & 1) ? uw : gw;
    float v = (srow < FFN_) ? src[(size_t)srow * D_ + c] : 0.f;
    d[i] = __float2half(v);
}

__global__ void conv_half(const float* __restrict__ src, __half* __restrict__ d)
{
    size_t i = ((size_t)blockIdx.x * blockDim.x + threadIdx.x) * 4;
    float4 v = *(const float4*)(src + i);
    __half hb[4] = { __float2half(v.x), __float2half(v.y),
                     __float2half(v.z), __float2half(v.w) };
    *(uint2*)(d + i) = *(uint2*)hb;
}

// ---------------------------------------------------------------------------
// fp16 GEMM with fused epilogues.
// mode&1: +bias. mode&2: +res. mode&4: fp16 out.
// mode&8: token-mix fusion (acc=glin; write xmix fp32 to C + bf16 split).
// mode&16: SwiGLU fusion (interleaved gate/up cols; write silu(g)*u fp16,
//          output width ldc applies to the HALF-width buffer).
// ---------------------------------------------------------------------------
#define MATB  10240
#define BUFB  (4 * MATB)
#define BUFBH (2 * MATB)

__global__ __launch_bounds__(256, 2) void mma_gemm_h(
    const __half* __restrict__ Af, const __half* __restrict__ Wf,
    const float* __restrict__ bias, const float* __restrict__ res,
    float* __restrict__ C,
    const float* __restrict__ xsrc,            // mode&8: original x
    __nv_bfloat16* __restrict__ bh16,          // mode&8: bf16 hi out
    __nv_bfloat16* __restrict__ bl16,          // mode&8: bf16 lo out
    int K, int NKB, int ldc, int mode)
{
    extern __shared__ char smem[];
    const uint32_t su = smem_u32(smem);
    const int tid = threadIdx.x;
    const int wid = tid >> 5, lane = tid & 31;
    const int wm = wid >> 2, wn = wid & 3;
    const int m0 = blockIdx.y * 128, n0 = blockIdx.x * 128;

    const uint32_t a_lrow = (uint32_t)(wm * 64 + (lane & 15)) * 80u + ((lane >> 4) * 16u);
    const uint32_t b_lrow = (uint32_t)(wn * 32 + ((lane >> 4) & 1) * 8 + (lane & 7)) * 80u
                          + (((lane >> 3) & 1) * 16u);

    float acc[4][4][4] = {};

    const int ch0 = tid * 2;
    #define LOAD_BUFH(kb, b) do {                                             \
        _Pragma("unroll")                                                     \
        for (int c = 0; c < 2; c++) {                                         \
            const int ch = ch0 + c;                                           \
            const int row = ch >> 2, sub = ch & 3;                            \
            const uint32_t dst = su + (b) * BUFBH + (uint32_t)row * 80u + sub * 16u; \
            const size_t asrc = (size_t)(m0 + row) * K + (kb) * 32 + sub * 8; \
            const size_t wsrc = (size_t)(n0 + row) * K + (kb) * 32 + sub * 8; \
            CP_ASYNC16(dst +    0, Af + asrc);                                \
            CP_ASYNC16(dst + MATB, Wf + wsrc);                                \
        }                                                                     \
    } while (0)

    LOAD_BUFH(0, 0);
    CP_COMMIT();
    LOAD_BUFH(1, 1);
    CP_COMMIT();

    int stage = 0;
    for (int kb = 0; kb < NKB; kb++) {
        if (kb + 1 < NKB) { CP_WAIT1(); } else { CP_WAIT0(); }
        __syncthreads();
        if (kb + 2 < NKB) {
            int ns = stage + 2; if (ns >= 3) ns -= 3;
            LOAD_BUFH(kb + 2, ns);
            CP_COMMIT();
        }

        const uint32_t sb = su + stage * BUFBH;
        #pragma unroll
        for (int ks = 0; ks < 2; ks++) {
            uint32_t af[4][4];
            uint32_t bh[2][4];
            #pragma unroll
            for (int mt = 0; mt < 4; mt++) {
                const uint32_t ra = sb + a_lrow + (uint32_t)mt * 16u * 80u + ks * 32u;
                LDSM_X4(af[mt][0], af[mt][1], af[mt][2], af[mt][3], ra);
            }
            #pragma unroll
            for (int np = 0; np < 2; np++) {
                const uint32_t rb = sb + MATB + b_lrow + (uint32_t)np * 16u * 80u + ks * 32u;
                LDSM_X4(bh[np][0], bh[np][1], bh[np][2], bh[np][3], rb);
            }
            #pragma unroll
            for (int mt = 0; mt < 4; mt++)
                #pragma unroll
                for (int nt = 0; nt < 4; nt++) {
                    const int np = nt >> 1, o = (nt & 1) * 2;
                    MMAH16816(acc[mt][nt], af[mt], bh[np][o], bh[np][o + 1]);
                }
        }
        stage++; if (stage >= 3) stage = 0;
    }

    const int qrow = lane >> 2, qcol = (lane & 3) * 2;
    #pragma unroll
    for (int mt = 0; mt < 4; mt++) {
        const int r0 = m0 + wm * 64 + mt * 16 + qrow;
        #pragma unroll
        for (int nt = 0; nt < 4; nt++) {
            const int c0 = n0 + wn * 32 + nt * 8 + qcol;
            float bx = 0.f, by = 0.f;
            if (mode & 1) { bx = bias[c0]; by = bias[c0 + 1]; }
            float2 v0 = make_float2(acc[mt][nt][0] + bx, acc[mt][nt][1] + by);
            float2 v1 = make_float2(acc[mt][nt][2] + bx, acc[mt][nt][3] + by);

            if (mode & 8) {
                // token-mix fusion: v = glin; compute xmix
                const int r1 = r0 + 8;
                const size_t xi0 = (size_t)r0 * ldc + c0;
                const size_t xi1 = (size_t)r1 * ldc + c0;
                float2 xv0 = *(const float2*)(xsrc + xi0);
                float2 xv1 = *(const float2*)(xsrc + xi1);
                float2 pv0 = make_float2(0.f, 0.f), pv1 = make_float2(0.f, 0.f);
                if ((r0 & (T_ - 1)) > 0) pv0 = *(const float2*)(xsrc + xi0 - D_);
                if ((r1 & (T_ - 1)) > 0) pv1 = *(const float2*)(xsrc + xi1 - D_);
                float g;
                float o0x, o0y, o1x, o1y;
                g = 1.f / (1.f + __expf(-v0.x)); o0x = (1.f - g) * xv0.x + g * pv0.x;
                g = 1.f / (1.f + __expf(-v0.y)); o0y = (1.f - g) * xv0.y + g * pv0.y;
                g = 1.f / (1.f + __expf(-v1.x)); o1x = (1.f - g) * xv1.x + g * pv1.x;
                g = 1.f / (1.f + __expf(-v1.y)); o1y = (1.f - g) * xv1.y + g * pv1.y;
                *(float2*)(C + xi0) = make_float2(o0x, o0y);
                *(float2*)(C + xi1) = make_float2(o1x, o1y);
                __nv_bfloat162 h0, h1, l0, l1;
                h0.x = __float2bfloat16(o0x); h0.y = __float2bfloat16(o0y);
                h1.x = __float2bfloat16(o1x); h1.y = __float2bfloat16(o1y);
                l0.x = __float2bfloat16(o0x - __bfloat162float(h0.x));
                l0.y = __float2bfloat16(o0y - __bfloat162float(h0.y));
                l1.x = __float2bfloat16(o1x - __bfloat162float(h1.x));
                l1.y = __float2bfloat16(o1y - __bfloat162float(h1.y));
                *(__nv_bfloat162*)(bh16 + xi0) = h0;
                *(__nv_bfloat162*)(bh16 + xi1) = h1;
                *(__nv_bfloat162*)(bl16 + xi0) = l0;
                *(__nv_bfloat162*)(bl16 + xi1) = l1;
            } else if (mode & 16) {
                // SwiGLU fusion: (v.x, v.y) = (gate, up) of channel c0/2
                __half* Ch = (__half*)C;
                const int cH = c0 >> 1;
                float a0 = v0.x / (1.f + __expf(-v0.x)) * v0.y;
                float a1 = v1.x / (1.f + __expf(-v1.x)) * v1.y;
                Ch[(size_t)r0 * ldc + cH]       = __float2half(a0);
                Ch[(size_t)(r0 + 8) * ldc + cH] = __float2half(a1);
            } else {
                const size_t i0 = (size_t)r0 * ldc + c0;
                const size_t i1 = (size_t)(r0 + 8) * ldc + c0;
                if (mode & 2) {
                    float2 r0v = *(const float2*)(res + i0);
                    float2 r1v = *(const float2*)(res + i1);
                    v0.x += r0v.x; v0.y += r0v.y;
                    v1.x += r1v.x; v1.y += r1v.y;
                }
                if (mode & 4) {
                    __half* Ch = (__half*)C;
                    __half2 h0, h1;
                    h0.x = __float2half(v0.x); h0.y = __float2half(v0.y);
                    h1.x = __float2half(v1.x); h1.y = __float2half(v1.y);
                    *(__half2*)(Ch + i0) = h0;
                    *(__half2*)(Ch + i1) = h1;
                } else {
                    *(float2*)(C + i0) = v0;
                    *(float2*)(C + i1) = v1;
                }
            }
        }
    }
    #undef LOAD_BUFH
}

// ---------------------------------------------------------------------------
// bf16 3-term split GEMM (dd projection only)
// ---------------------------------------------------------------------------
__global__ __launch_bounds__(256, 1) void mma_gemm(
    const __nv_bfloat16* __restrict__ Ah, const __nv_bfloat16* __restrict__ Al,
    const __nv_bfloat16* __restrict__ Wh, const __nv_bfloat16* __restrict__ Wl,
    const float* __restrict__ bias,
    float* __restrict__ C, int K, int NKB, int ldc)
{
    extern __shared__ char smem[];
    const uint32_t su = smem_u32(smem);
    const int tid = threadIdx.x;
    const int wid = tid >> 5, lane = tid & 31;
    const int wm = wid >> 2, wn = wid & 3;
    const int m0 = blockIdx.y * 128, n0 = blockIdx.x * 128;

    const uint32_t a_lrow = (uint32_t)(wm * 64 + (lane & 15)) * 80u + ((lane >> 4) * 16u);
    const uint32_t b_lrow = (uint32_t)(wn * 32 + ((lane >> 4) & 1) * 8 + (lane & 7)) * 80u
                          + (((lane >> 3) & 1) * 16u);

    float acc[4][4][4] = {};

    const int ch0 = tid * 2;
    #define LOAD_BUF(kb, b) do {                                              \
        _Pragma("unroll")                                                     \
        for (int c = 0; c < 2; c++) {                                         \
            const int ch = ch0 + c;                                           \
            const int row = ch >> 2, sub = ch & 3;                            \
            const uint32_t dst = su + (b) * BUFB + (uint32_t)row * 80u + sub * 16u; \
            const size_t asrc = (size_t)(m0 + row) * K + (kb) * 32 + sub * 8; \
            const size_t wsrc = (size_t)(n0 + row) * K + (kb) * 32 + sub * 8; \
            CP_ASYNC16(dst +        0, Ah + asrc);                            \
            CP_ASYNC16(dst +     MATB, Al + asrc);                            \
            CP_ASYNC16(dst + 2 * MATB, Wh + wsrc);                            \
            CP_ASYNC16(dst + 3 * MATB, Wl + wsrc);                            \
        }                                                                     \
    } while (0)

    LOAD_BUF(0, 0);
    CP_COMMIT();
    LOAD_BUF(1, 1);
    CP_COMMIT();

    int stage = 0;
    for (int kb = 0; kb < NKB; kb++) {
        if (kb + 1 < NKB) { CP_WAIT1(); } else { CP_WAIT0(); }
        __syncthreads();
        if (kb + 2 < NKB) {
            int ns = stage + 2; if (ns >= 3) ns -= 3;
            LOAD_BUF(kb + 2, ns);
            CP_COMMIT();
        }

        const uint32_t sb = su + stage * BUFB;
        #pragma unroll
        for (int ks = 0; ks < 2; ks++) {
            uint32_t ah[4][4], al[4][4];
            uint32_t bh[2][4], bl[2][4];
            #pragma unroll
            for (int mt = 0; mt < 4; mt++) {
                const uint32_t ra = sb + a_lrow + (uint32_t)mt * 16u * 80u + ks * 32u;
                LDSM_X4(ah[mt][0], ah[mt][1], ah[mt][2], ah[mt][3], ra);
                LDSM_X4(al[mt][0], al[mt][1], al[mt][2], al[mt][3], ra + MATB);
            }
            #pragma unroll
            for (int np = 0; np < 2; np++) {
                const uint32_t rb = sb + 2 * MATB + b_lrow + (uint32_t)np * 16u * 80u + ks * 32u;
                LDSM_X4(bh[np][0], bh[np][1], bh[np][2], bh[np][3], rb);
                LDSM_X4(bl[np][0], bl[np][1], bl[np][2], bl[np][3], rb + MATB);
            }
            #pragma unroll
            for (int mt = 0; mt < 4; mt++)
                #pragma unroll
                for (int nt = 0; nt < 4; nt++) {
                    const int np = nt >> 1, o = (nt & 1) * 2;
                    MMA16816(acc[mt][nt], ah[mt], bh[np][o], bh[np][o + 1]);
                    MMA16816(acc[mt][nt], ah[mt], bl[np][o], bl[np][o + 1]);
                    MMA16816(acc[mt][nt], al[mt], bh[np][o], bh[np][o + 1]);
                }
        }
        stage++; if (stage >= 3) stage = 0;
    }

    const int qrow = lane >> 2, qcol = (lane & 3) * 2;
    #pragma unroll
    for (int mt = 0; mt < 4; mt++) {
        const int r0 = m0 + wm * 64 + mt * 16 + qrow;
        #pragma unroll
        for (int nt = 0; nt < 4; nt++) {
            const int c0 = n0 + wn * 32 + nt * 8 + qcol;
            float bx = bias[c0], by = bias[c0 + 1];
            *(float2*)(C + (size_t)r0 * ldc + c0) =
                make_float2(acc[mt][nt][0] + bx, acc[mt][nt][1] + by);
            *(float2*)(C + (size_t)(r0 + 8) * ldc + c0) =
                make_float2(acc[mt][nt][2] + bx, acc[mt][nt][3] + by);
        }
    }
    #undef LOAD_BUF
}

// ---------------------------------------------------------------------------
// RMSNorm -> single fp16 output
// ---------------------------------------------------------------------------
__global__ __launch_bounds__(256) void rmsnorm_half_kernel(
    const float* __restrict__ x, const float* __restrict__ w,
    __half* __restrict__ oh)
{
    const int row = blockIdx.x;
    const int tid = threadIdx.x;
    const float* xr = x + (size_t)row * D_;
    float4 v = *(const float4*)(xr + tid * 4);
    float s = v.x * v.x + v.y * v.y + v.z * v.z + v.w * v.w;
    #pragma unroll
    for (int m = 16; m > 0; m >>= 1) s += __shfl_xor_sync(0xffffffffu, s, m);
    __shared__ float red[8];
    if ((tid & 31) == 0) red[tid >> 5] = s;
    __syncthreads();
    if (tid < 32) {
        float t = (tid < 8) ? red[tid] : 0.f;
        #pragma unroll
        for (int m = 4; m > 0; m >>= 1) t += __shfl_xor_sync(0xffffffffu, t, m);
        if (tid == 0) red[0] = t;
    }
    __syncthreads();
    const float inv = rsqrtf(red[0] / (float)D_ + EPS_);
    float4 wv = *(const float4*)(w + tid * 4);
    __half hb[4] = { __float2half(v.x * inv * wv.x), __float2half(v.y * inv * wv.y),
                     __float2half(v.z * inv * wv.z), __float2half(v.w * inv * wv.w) };
    *(uint2*)(oh + (size_t)row * D_ + tid * 4) = *(uint2*)hb;
}

// ---------------------------------------------------------------------------
// 3-phase cumsum
// ---------------------------------------------------------------------------
__global__ void cumsumA(const float* __restrict__ dd, float* __restrict__ cs)
{
    const int c = threadIdx.x;
    const int blk = blockIdx.x;
    const int b = blk >> 4, ch = blk & 15;
    size_t base = ((size_t)b * T_ + ch * 128) * 256 + c;
    float s = 0.f;
    #pragma unroll 8
    for (int t = 0; t < 128; t++) { s += dd[base]; base += 256; }
    cs[(size_t)blk * 256 + c] = s;
}
__global__ void cumsumB(float* __restrict__ cs)
{
    const int c = threadIdx.x;
    const int b = blockIdx.x;
    float run = 0.f;
    #pragma unroll
    for (int ch = 0; ch < 16; ch++) {
        size_t i = ((size_t)b * 16 + ch) * 256 + c;
        float t = cs[i];
        cs[i] = run;
        run += t;
    }
}
__global__ void cumsumC(float* __restrict__ dd, const float* __restrict__ cs)
{
    const int c = threadIdx.x;
    const int blk = blockIdx.x;
    const int b = blk >> 4, ch = blk & 15;
    float acc = cs[(size_t)blk * 256 + c];
    size_t base = ((size_t)b * T_ + ch * 128) * 256 + c;
    #pragma unroll 8
    for (int t = 0; t < 128; t++) { acc += dd[base]; dd[base] = acc; base += 256; }
}

// ---------------------------------------------------------------------------
// q/k head rmsnorm + hybrid rope + head-major scatter (fp16 in/out)
// ---------------------------------------------------------------------------
__global__ __launch_bounds__(256) void qkv_transform_h(
    const __half* __restrict__ qkv, const float* __restrict__ ddcum,
    const float* __restrict__ rc, const float* __restrict__ rs,
    const float* __restrict__ qnw, const float* __restrict__ knw,
    const float* __restrict__ qpb, const float* __restrict__ kpb,
    __half* __restrict__ qt, __half* __restrict__ kt, __half* __restrict__ vt)
{
    const int w = blockIdx.x * 8 + (threadIdx.x >> 5);
    const int lane = threadIdx.x & 31;
    const int b = w >> 15;
    const int rem = w & 32767;
    const int t = rem >> 4;
    const int h = rem & 15;

    const size_t base = ((size_t)(b * T_ + t) * 3) * D_ + h * DH_;
    float q0 = __half2float(qkv[base + lane]);
    float q1 = __half2float(qkv[base + 32 + lane]);
    float k0 = __half2float(qkv[base + D_ + lane]);
    float k1 = __half2float(qkv[base + D_ + 32 + lane]);
    __half v0 = qkv[base + 2 * D_ + lane];
    __half v1 = qkv[base + 2 * D_ + 32 + lane];

    float sq = q0 * q0 + q1 * q1;
    float sk = k0 * k0 + k1 * k1;
    #pragma unroll
    for (int m = 16; m > 0; m >>= 1) {
        sq += __shfl_xor_sync(0xffffffffu, sq, m);
        sk += __shfl_xor_sync(0xffffffffu, sk, m);
    }
    const float rq = rsqrtf(sq / 64.f + EPS_);
    const float rk = rsqrtf(sk / 64.f + EPS_);
    q0 *= rq * qnw[lane] * qpb[lane];
    q1 *= rq * qnw[lane + 32] * qpb[lane + 32];
    k0 *= rk * knw[lane] * kpb[lane];
    k1 *= rk * knw[lane + 32] * kpb[lane + 32];

    const int j = lane & 15;
    const float c = rc[t * 32 + j], s = rs[t * 32 + j];
    const float ang = ddcum[((size_t)(b * T_ + t)) * 256 + h * 16 + j];
    float s2, c2;
    sincosf(ang, &s2, &c2);

    const float qp0 = __shfl_xor_sync(0xffffffffu, q0, 16);
    const float qp1 = __shfl_xor_sync(0xffffffffu, q1, 16);
    const float kp0 = __shfl_xor_sync(0xffffffffu, k0, 16);
    const float kp1 = __shfl_xor_sync(0xffffffffu, k1, 16);
    float oq0, oq1, ok0, ok1;
    if (lane < 16) {
        oq0 = q0 * c - qp0 * s;  oq1 = q1 * c2 - qp1 * s2;
        ok0 = k0 * c - kp0 * s;  ok1 = k1 * c2 - kp1 * s2;
    } else {
        oq0 = q0 * c + qp0 * s;  oq1 = q1 * c2 + qp1 * s2;
        ok0 = k0 * c + kp0 * s;  ok1 = k1 * c2 + kp1 * s2;
    }

    const size_t ob = ((size_t)(b * NH_ + h) * T_ + t) * DH_;
    qt[ob + lane]      = __float2half(oq0 * 0.125f);
    qt[ob + 32 + lane] = __float2half(oq1 * 0.125f);
    kt[ob + lane]      = __float2half(ok0);
    kt[ob + 32 + lane] = __float2half(ok1);
    vt[ob + lane]      = v0;
    vt[ob + 32 + lane] = v1;
}

// ---------------------------------------------------------------------------
// fp16 flash attention (register-resident P), 2 CTAs/SM
// ---------------------------------------------------------------------------
#define FSMEMH (64 * 72 * 2 + 32 * 72 * 4)

__global__ __launch_bounds__(256, 2) void flash_h(
    const __half* __restrict__ qt, const __half* __restrict__ kt,
    const __half* __restrict__ vt, __half* __restrict__ yh)
{
    extern __shared__ __half fsmh[];
    __half* Ks = fsmh;
    uint32_t* Vs2 = (uint32_t*)(fsmh + 64 * 72);

    const int tid = threadIdx.x, lane = tid & 31, w = tid >> 5;
    const int bx = gridDim.x - 1 - blockIdx.x;
    const int bh = blockIdx.y;
    const int b = bh >> 4, h = bh & 15;
    const int m0 = bx * 128;

    const __half* Qb = qt + (size_t)bh * T_ * DH_;
    const __half* Kb = kt + (size_t)bh * T_ * DH_;
    const __half* Vb = vt + (size_t)bh * T_ * DH_;

    const int r1 = m0 + w * 16 + (lane >> 2);
    uint32_t qf[4][4];
    {
        const __half* q1 = Qb + (size_t)r1 * DH_;
        const __half* q2 = q1 + 8 * DH_;
        #pragma unroll
        for (int c = 0; c < 4; c++) {
            const int col = c * 16 + 2 * (lane & 3);
            qf[c][0] = *(const uint32_t*)(q1 + col);
            qf[c][1] = *(const uint32_t*)(q2 + col);
            qf[c][2] = *(const uint32_t*)(q1 + col + 8);
            qf[c][3] = *(const uint32_t*)(q2 + col + 8);
        }
    }

    float mi[2] = { -1e30f, -1e30f }, li[2] = { 0.f, 0.f };
    float O[8][4] = {};

    const int ntiles = 2 * bx + 2;
    for (int nt = 0; nt < ntiles; nt++) {
        const int n0 = nt * 64;
        __syncthreads();
        {
            const int key = tid >> 2, db = (tid & 3) * 16;
            const __half* kp = Kb + (size_t)(n0 + key) * DH_ + db;
            *(uint4*)&Ks[key * 72 + db]     = *(const uint4*)kp;
            *(uint4*)&Ks[key * 72 + db + 8] = *(const uint4*)(kp + 8);
            const int kp2 = tid >> 3, dv = (tid & 7) * 8;
            const __half* v0p = Vb + (size_t)(n0 + 2 * kp2) * DH_ + dv;
            const __half* v1p = v0p + DH_;
            __half a8[8], b8[8];
            *(uint4*)a8 = *(const uint4*)v0p;
            *(uint4*)b8 = *(const uint4*)v1p;
            uint32_t pk[8];
            #pragma unroll
            for (int i = 0; i < 8; i++) {
                __half2 t2; t2.x = a8[i]; t2.y = b8[i];
                pk[i] = *(uint32_t*)&t2;
            }
            *(uint4*)&Vs2[kp2 * 72 + dv]     = *(uint4*)pk;
            *(uint4*)&Vs2[kp2 * 72 + dv + 4] = *(uint4*)(pk + 4);
        }
        __syncthreads();

        float S[8][4] = {};
        #pragma unroll
        for (int c = 0; c < 4; c++) {
            #pragma unroll
            for (int n8 = 0; n8 < 8; n8++) {
                const __half* kr = &Ks[(n8 * 8 + (lane >> 2)) * 72 + c * 16 + 2 * (lane & 3)];
                uint32_t b0 = *(const uint32_t*)kr;
                uint32_t b1 = *(const uint32_t*)(kr + 8);
                MMAH16816(S[n8], qf[c], b0, b1);
            }
        }
        if (nt >= 2 * bx) {
            #pragma unroll
            for (int n8 = 0; n8 < 8; n8++) {
                const int cb = n0 + n8 * 8 + 2 * (lane & 3);
                if (cb     > r1)     S[n8][0] = -1e30f;
                if (cb + 1 > r1)     S[n8][1] = -1e30f;
                if (cb     > r1 + 8) S[n8][2] = -1e30f;
                if (cb + 1 > r1 + 8) S[n8][3] = -1e30f;
            }
        }
        #pragma unroll
        for (int half = 0; half < 2; half++) {
            float mx = -1e30f;
            #pragma unroll
            for (int n8 = 0; n8 < 8; n8++)
                mx = fmaxf(mx, fmaxf(S[n8][half * 2], S[n8][half * 2 + 1]));
            mx = fmaxf(mx, __shfl_xor_sync(0xffffffffu, mx, 1));
            mx = fmaxf(mx, __shfl_xor_sync(0xffffffffu, mx, 2));
            const float mnew = fmaxf(mi[half], mx);
            const float corr = __expf(mi[half] - mnew);
            float rsum = 0.f;
            #pragma unroll
            for (int n8 = 0; n8 < 8; n8++) {
                float e0 = __expf(S[n8][half * 2]     - mnew);
                float e1 = __expf(S[n8][half * 2 + 1] - mnew);
                S[n8][half * 2] = e0; S[n8][half * 2 + 1] = e1;
                rsum += e0 + e1;
            }
            rsum += __shfl_xor_sync(0xffffffffu, rsum, 1);
            rsum += __shfl_xor_sync(0xffffffffu, rsum, 2);
            li[half] = li[half] * corr + rsum;
            mi[half] = mnew;
            #pragma unroll
            for (int n8 = 0; n8 < 8; n8++) {
                O[n8][half * 2]     *= corr;
                O[n8][half * 2 + 1] *= corr;
            }
        }
        #pragma unroll
        for (int c = 0; c < 4; c++) {
            uint32_t a[4];
            a[0] = h2bits(S[2 * c][0],     S[2 * c][1]);
            a[1] = h2bits(S[2 * c][2],     S[2 * c][3]);
            a[2] = h2bits(S[2 * c + 1][0], S[2 * c + 1][1]);
            a[3] = h2bits(S[2 * c + 1][2], S[2 * c + 1][3]);
            const uint32_t* vr0 = &Vs2[((lane & 3) + c * 8) * 72 + (lane >> 2)];
            const uint32_t* vr1 = vr0 + 4 * 72;
            #pragma unroll
            for (int n8 = 0; n8 < 8; n8++) {
                MMAH16816(O[n8], a, vr0[n8 * 8], vr1[n8 * 8]);
            }
        }
    }

    const float inv0 = 1.f / li[0], inv1 = 1.f / li[1];
    const size_t o1 = ((size_t)(b * T_ + r1)) * D_ + h * DH_ + 2 * (lane & 3);
    const size_t o2 = o1 + 8 * D_;
    #pragma unroll
    for (int n8 = 0; n8 < 8; n8++) {
        __half2 h0, h1;
        h0.x = __float2half(O[n8][0] * inv0); h0.y = __float2half(O[n8][1] * inv0);
        h1.x = __float2half(O[n8][2] * inv1); h1.y = __float2half(O[n8][3] * inv1);
        *(__half2*)(yh + o1 + n8 * 8) = h0;
        *(__half2*)(yh + o2 + n8 * 8) = h1;
    }
}

// ---------------------------------------------------------------------------
// Launch
// ---------------------------------------------------------------------------
static inline int cdiv(long long a, long long b) { return (int)((a + b - 1) / b); }

extern "C" void kernel_launch(void* const* d_in, const int* in_sizes, int n_in,
                              void* d_out, int out_size)
{
    const float* x     = (const float*)d_in[0];
    const float* rc    = (const float*)d_in[1];
    const float* rs    = (const float*)d_in[2];
    const float* lerpw = (const float*)d_in[3];
    const float* lerpb = (const float*)d_in[4];
    const float* anw   = (const float*)d_in[5];
    const float* wqkv  = (const float*)d_in[6];
    const float* qnw   = (const float*)d_in[7];
    const float* knw   = (const float*)d_in[8];
    const float* qpb   = (const float*)d_in[9];
    const float* kpb   = (const float*)d_in[10];
    const float* ddw   = (const float*)d_in[11];
    const float* ddb   = (const float*)d_in[12];
    const float* wo    = (const float*)d_in[13];
    const float* mnw   = (const float*)d_in[14];
    const float* gw    = (const float*)d_in[15];
    const float* uw    = (const float*)d_in[16];
    const float* dw    = (const float*)d_in[17];
    float* out = (float*)d_out;

    float *xmix, *dd, *cs, *x2;
    __half *qkvh, *qth, *kth, *vth, *guh;
    __nv_bfloat16 *ah, *al, *wh, *wl;
    __half *af, *wf;
    cudaGetSymbolAddress((void**)&xmix, s_xmix);
    cudaGetSymbolAddress((void**)&dd,   s_dd);
    cudaGetSymbolAddress((void**)&cs,   s_csum);
    cudaGetSymbolAddress((void**)&x2,   s_x2);
    cudaGetSymbolAddress((void**)&qkvh, s_qkvh);
    cudaGetSymbolAddress((void**)&qth,  s_qth);
    cudaGetSymbolAddress((void**)&kth,  s_kth);
    cudaGetSymbolAddress((void**)&vth,  s_vth);
    cudaGetSymbolAddress((void**)&guh,  s_guh);
    cudaGetSymbolAddress((void**)&ah,   g_ah);
    cudaGetSymbolAddress((void**)&al,   g_al);
    cudaGetSymbolAddress((void**)&wh,   g_wh);
    cudaGetSymbolAddress((void**)&wl,   g_wl);
    cudaGetSymbolAddress((void**)&af,   g_af);
    cudaGetSymbolAddress((void**)&wf,   g_wf);

    cudaFuncSetAttribute(mma_gemm,
                         cudaFuncAttributeMaxDynamicSharedMemorySize, 3 * BUFB);
    cudaFuncSetAttribute(mma_gemm_h,
                         cudaFuncAttributeMaxDynamicSharedMemorySize, 3 * BUFBH);
    cudaFuncSetAttribute(flash_h,
                         cudaFuncAttributeMaxDynamicSharedMemorySize, FSMEMH);

    const dim3 blk(256);
    const int GSM  = 3 * BUFB;
    const int GSMH = 3 * BUFBH;

    #define CONVH(src, d, n) \
        conv_half<<<(int)(((long long)(n) / 4) / 256), blk>>>(src, d)
    #define CONVW(src, d, r, c, rp, cp) \
        conv_whalf<<<cdiv((long long)(rp) * (cp), 256), blk>>>(src, d, r, c, rp, cp)

    // 1. fused: glin = x @ lerp_w^T + b; xmix = mix(x, sigmoid(glin)) + bf16 split
    CONVH(x, af, (long long)M_ * D_);
    CONVW(lerpw, wf, D_, D_, D_, D_);
    mma_gemm_h<<<dim3(8, 32), blk, GSMH>>>(af, wf, lerpb, nullptr, xmix,
                                           x, ah, al, D_, 32, D_, 1 | 8);
    // 2. dd = xmix @ dd_w^T + dd_b (bf16 3-term)
    convsplit<<<cdiv(256LL * D_, 256), blk>>>(ddw, wh, wl, 256, D_, 256, D_);
    mma_gemm<<<dim3(2, 32), blk, GSM>>>(ah, al, wh, wl, ddb, dd, D_, 32, 256);
    // 3. cumsum along T
    cumsumA<<<B_ * 16, blk>>>(dd, cs);
    cumsumB<<<B_, blk>>>(cs);
    cumsumC<<<B_ * 16, blk>>>(dd, cs);
    // 4. h = rmsnorm(xmix) -> fp16
    rmsnorm_half_kernel<<<M_, blk>>>(xmix, anw, af);
    // 5. qkv = h @ w_qkv^T -> fp16
    CONVW(wqkv, wf, 3 * D_, D_, 3 * D_, D_);
    mma_gemm_h<<<dim3(24, 32), blk, GSMH>>>(af, wf, nullptr, nullptr,
                                            (float*)qkvh, nullptr, nullptr, nullptr,
                                            D_, 32, 3 * D_, 4);
    // 6. q/k transform
    qkv_transform_h<<<(B_ * T_ * NH_) / 8, blk>>>(qkvh, dd, rc, rs, qnw, knw,
                                                  qpb, kpb, qth, kth, vth);
    // 7. flash attention -> y fp16
    flash_h<<<dim3(T_ / 128, B_ * NH_), blk, FSMEMH>>>(qth, kth, vth, af);
    // 8. x2 = xmix + y @ w_o^T
    CONVW(wo, wf, D_, D_, D_, D_);
    mma_gemm_h<<<dim3(8, 32), blk, GSMH>>>(af, wf, nullptr, xmix, x2,
                                           nullptr, nullptr, nullptr, D_, 32, D_, 2);
    // 9. h = rmsnorm(x2) -> fp16
    rmsnorm_half_kernel<<<M_, blk>>>(x2, mnw, af);
    // 10. fused gate|up GEMM (interleaved) -> act fp16 directly
    conv_wgu<<<cdiv((long long)2 * FFNP * D_, 256), blk>>>(gw, uw, wf);
    mma_gemm_h<<<dim3(44, 32), blk, GSMH>>>(af, wf, nullptr, nullptr,
                                            (float*)guh, nullptr, nullptr, nullptr,
                                            D_, 32, FFNP, 16);
    // 11. out = x2 + act @ down_w^T
    CONVW(dw, wf, D_, FFN_, D_, FFNP);
    mma_gemm_h<<<dim3(8, 32), blk, GSMH>>>(guh, wf, nullptr, x2, out,
                                           nullptr, nullptr, nullptr, FFNP, 88, D_, 2);
}

// round 12
// speedup vs baseline: 1.1002x; 1.1002x over previous
#include <cuda_runtime.h>
#include <cuda_bf16.h>
#include <cuda_fp16.h>
#include <math.h>
#include <stdint.h>

// ---------------------------------------------------------------------------
// Problem constants
// ---------------------------------------------------------------------------
#define B_   2
#define T_   2048
#define D_   1024
#define NH_  16
#define DH_  64
#define FFN_ 2736
#define FFNP 2816
#define M_   (B_ * T_)
#define EPS_ 1e-6f

// ---------------------------------------------------------------------------
// PTX helpers
// ---------------------------------------------------------------------------
__device__ __forceinline__ uint32_t smem_u32(const void* p) {
    uint32_t a;
    asm("{ .reg .u64 t; cvta.to.shared.u64 t, %1; cvt.u32.u64 %0, t; }"
        : "=r"(a) : "l"(p));
    return a;
}
#define CP_ASYNC16(dst, src) \
    asm volatile("cp.async.cg.shared.global [%0], [%1], 16;" :: "r"(dst), "l"(src))
#define CP_COMMIT() asm volatile("cp.async.commit_group;" ::: "memory")
#define CP_WAIT0()  asm volatile("cp.async.wait_group 0;" ::: "memory")
#define CP_WAIT1()  asm volatile("cp.async.wait_group 1;" ::: "memory")
#define LDSM_X4(r0, r1, r2, r3, addr) \
    asm volatile("ldmatrix.sync.aligned.m8n8.x4.shared.b16 {%0,%1,%2,%3}, [%4];" \
                 : "=r"(r0), "=r"(r1), "=r"(r2), "=r"(r3) : "r"(addr))
#define MMA16816(d, a, b0, b1) \
    asm volatile("mma.sync.aligned.m16n8k16.row.col.f32.bf16.bf16.f32 " \
                 "{%0,%1,%2,%3},{%4,%5,%6,%7},{%8,%9},{%0,%1,%2,%3};" \
                 : "+f"((d)[0]), "+f"((d)[1]), "+f"((d)[2]), "+f"((d)[3]) \
                 : "r"((a)[0]), "r"((a)[1]), "r"((a)[2]), "r"((a)[3]), \
                   "r"(b0), "r"(b1))
#define MMAH16816(d, a, b0, b1) \
    asm volatile("mma.sync.aligned.m16n8k16.row.col.f32.f16.f16.f32 " \
                 "{%0,%1,%2,%3},{%4,%5,%6,%7},{%8,%9},{%0,%1,%2,%3};" \
                 : "+f"((d)[0]), "+f"((d)[1]), "+f"((d)[2]), "+f"((d)[3]) \
                 : "r"((a)[0]), "r"((a)[1]), "r"((a)[2]), "r"((a)[3]), \
                   "r"(b0), "r"(b1))
__device__ __forceinline__ uint32_t h2bits(float a, float b) {
    __half2 t = __floats2half2_rn(a, b);
    return *(uint32_t*)&t;
}

// ---------------------------------------------------------------------------
// Device scratch
// ---------------------------------------------------------------------------
__device__ float s_xmix[M_ * D_];
__device__ float s_dd  [M_ * NH_ * 16];
__device__ float s_csum[B_ * 16 * 256];
__device__ float s_x2  [M_ * D_];
__device__ __half s_qkvh[(size_t)M_ * 3 * D_];
__device__ __half s_qth [B_ * NH_ * T_ * DH_];
__device__ __half s_kth [B_ * NH_ * T_ * DH_];
__device__ __half s_vth [B_ * NH_ * T_ * DH_];
__device__ __half s_guh [(size_t)M_ * FFNP];
// bf16 split buffers (dd path only)
__device__ __nv_bfloat16 g_ah[(size_t)M_ * D_];
__device__ __nv_bfloat16 g_al[(size_t)M_ * D_];
__device__ __nv_bfloat16 g_wh[256 * D_];
__device__ __nv_bfloat16 g_wl[256 * D_];
// fp16 buffers (main GEMM path). wf regions:
//   [0]                : lerp / wqkv / wo (reused sequentially, <= 3*D*D)
//   [3*D*D]            : interleaved gate|up  (2*FFNP*D)
//   [3*D*D + 2*FFNP*D] : down weights         (D*FFNP)
#define WF0   0
#define WFGU  ((size_t)3 * D_ * D_)
#define WFDW  (WFGU + (size_t)2 * FFNP * D_)
__device__ __half g_af[(size_t)M_ * FFNP];
__device__ __half g_wf[WFDW + (size_t)D_ * FFNP];

// ---------------------------------------------------------------------------
// Streams/events for graph-level parallelism (static init; reused every call)
// ---------------------------------------------------------------------------
struct SideStream {
    cudaStream_t s2;
    cudaEvent_t evA, evB1, evB2;
    SideStream() {
        cudaStreamCreateWithFlags(&s2, cudaStreamNonBlocking);
        cudaEventCreateWithFlags(&evA,  cudaEventDisableTiming);
        cudaEventCreateWithFlags(&evB1, cudaEventDisableTiming);
        cudaEventCreateWithFlags(&evB2, cudaEventDisableTiming);
    }
};
static SideStream g_ss;

// ---------------------------------------------------------------------------
// conversions
// ---------------------------------------------------------------------------
__global__ void convsplit(const float* __restrict__ src,
                          __nv_bfloat16* __restrict__ h,
                          __nv_bfloat16* __restrict__ l,
                          int rows, int cols, int rows_pad, int cols_pad)
{
    size_t i = (size_t)blockIdx.x * blockDim.x + threadIdx.x;
    size_t total = (size_t)rows_pad * cols_pad;
    if (i >= total) return;
    int r = (int)(i / cols_pad);
    int c = (int)(i - (size_t)r * cols_pad);
    float v = (r < rows && c < cols) ? src[(size_t)r * cols + c] : 0.f;
    __nv_bfloat16 hi = __float2bfloat16(v);
    h[i] = hi;
    l[i] = __float2bfloat16(v - __bfloat162float(hi));
}

__global__ void conv_whalf(const float* __restrict__ src,
                           __half* __restrict__ d,
                           int rows, int cols, int rows_pad, int cols_pad)
{
    size_t i = (size_t)blockIdx.x * blockDim.x + threadIdx.x;
    size_t total = (size_t)rows_pad * cols_pad;
    if (i >= total) return;
    int r = (int)(i / cols_pad);
    int c = (int)(i - (size_t)r * cols_pad);
    float v = (r < rows && c < cols) ? src[(size_t)r * cols + c] : 0.f;
    d[i] = __float2half(v);
}

__global__ void conv_wgu(const float* __restrict__ gw,
                         const float* __restrict__ uw,
                         __half* __restrict__ d)
{
    size_t i = (size_t)blockIdx.x * blockDim.x + threadIdx.x;
    if (i >= (size_t)2 * FFNP * D_) return;
    int r = (int)(i / D_);
    int c = (int)(i - (size_t)r * D_);
    int srow = r >> 1;
    const float* src = (r & 1) ? uw : gw;
    float v = (srow < FFN_) ? src[(size_t)srow * D_ + c] : 0.f;
    d[i] = __float2half(v);
}

__global__ void conv_half(const float* __restrict__ src, __half* __restrict__ d)
{
    size_t i = ((size_t)blockIdx.x * blockDim.x + threadIdx.x) * 4;
    float4 v = *(const float4*)(src + i);
    __half hb[4] = { __float2half(v.x), __float2half(v.y),
                     __float2half(v.z), __float2half(v.w) };
    *(uint2*)(d + i) = *(uint2*)hb;
}

// ---------------------------------------------------------------------------
// fp16 GEMM with fused epilogues (as R11)
// ---------------------------------------------------------------------------
#define MATB  10240
#define BUFB  (4 * MATB)
#define BUFBH (2 * MATB)

__global__ __launch_bounds__(256, 2) void mma_gemm_h(
    const __half* __restrict__ Af, const __half* __restrict__ Wf,
    const float* __restrict__ bias, const float* __restrict__ res,
    float* __restrict__ C,
    const float* __restrict__ xsrc,
    __nv_bfloat16* __restrict__ bh16,
    __nv_bfloat16* __restrict__ bl16,
    int K, int NKB, int ldc, int mode)
{
    extern __shared__ char smem[];
    const uint32_t su = smem_u32(smem);
    const int tid = threadIdx.x;
    const int wid = tid >> 5, lane = tid & 31;
    const int wm = wid >> 2, wn = wid & 3;
    const int m0 = blockIdx.y * 128, n0 = blockIdx.x * 128;

    const uint32_t a_lrow = (uint32_t)(wm * 64 + (lane & 15)) * 80u + ((lane >> 4) * 16u);
    const uint32_t b_lrow = (uint32_t)(wn * 32 + ((lane >> 4) & 1) * 8 + (lane & 7)) * 80u
                          + (((lane >> 3) & 1) * 16u);

    float acc[4][4][4] = {};

    const int ch0 = tid * 2;
    #define LOAD_BUFH(kb, b) do {                                             \
        _Pragma("unroll")                                                     \
        for (int c = 0; c < 2; c++) {                                         \
            const int ch = ch0 + c;                                           \
            const int row = ch >> 2, sub = ch & 3;                            \
            const uint32_t dst = su + (b) * BUFBH + (uint32_t)row * 80u + sub * 16u; \
            const size_t asrc = (size_t)(m0 + row) * K + (kb) * 32 + sub * 8; \
            const size_t wsrc = (size_t)(n0 + row) * K + (kb) * 32 + sub * 8; \
            CP_ASYNC16(dst +    0, Af + asrc);                                \
            CP_ASYNC16(dst + MATB, Wf + wsrc);                                \
        }                                                                     \
    } while (0)

    LOAD_BUFH(0, 0);
    CP_COMMIT();
    LOAD_BUFH(1, 1);
    CP_COMMIT();

    int stage = 0;
    for (int kb = 0; kb < NKB; kb++) {
        if (kb + 1 < NKB) { CP_WAIT1(); } else { CP_WAIT0(); }
        __syncthreads();
        if (kb + 2 < NKB) {
            int ns = stage + 2; if (ns >= 3) ns -= 3;
            LOAD_BUFH(kb + 2, ns);
            CP_COMMIT();
        }

        const uint32_t sb = su + stage * BUFBH;
        #pragma unroll
        for (int ks = 0; ks < 2; ks++) {
            uint32_t af[4][4];
            uint32_t bh[2][4];
            #pragma unroll
            for (int mt = 0; mt < 4; mt++) {
                const uint32_t ra = sb + a_lrow + (uint32_t)mt * 16u * 80u + ks * 32u;
                LDSM_X4(af[mt][0], af[mt][1], af[mt][2], af[mt][3], ra);
            }
            #pragma unroll
            for (int np = 0; np < 2; np++) {
                const uint32_t rb = sb + MATB + b_lrow + (uint32_t)np * 16u * 80u + ks * 32u;
                LDSM_X4(bh[np][0], bh[np][1], bh[np][2], bh[np][3], rb);
            }
            #pragma unroll
            for (int mt = 0; mt < 4; mt++)
                #pragma unroll
                for (int nt = 0; nt < 4; nt++) {
                    const int np = nt >> 1, o = (nt & 1) * 2;
                    MMAH16816(acc[mt][nt], af[mt], bh[np][o], bh[np][o + 1]);
                }
        }
        stage++; if (stage >= 3) stage = 0;
    }

    const int qrow = lane >> 2, qcol = (lane & 3) * 2;
    #pragma unroll
    for (int mt = 0; mt < 4; mt++) {
        const int r0 = m0 + wm * 64 + mt * 16 + qrow;
        #pragma unroll
        for (int nt = 0; nt < 4; nt++) {
            const int c0 = n0 + wn * 32 + nt * 8 + qcol;
            float bx = 0.f, by = 0.f;
            if (mode & 1) { bx = bias[c0]; by = bias[c0 + 1]; }
            float2 v0 = make_float2(acc[mt][nt][0] + bx, acc[mt][nt][1] + by);
            float2 v1 = make_float2(acc[mt][nt][2] + bx, acc[mt][nt][3] + by);

            if (mode & 8) {
                const int r1 = r0 + 8;
                const size_t xi0 = (size_t)r0 * ldc + c0;
                const size_t xi1 = (size_t)r1 * ldc + c0;
                float2 xv0 = *(const float2*)(xsrc + xi0);
                float2 xv1 = *(const float2*)(xsrc + xi1);
                float2 pv0 = make_float2(0.f, 0.f), pv1 = make_float2(0.f, 0.f);
                if ((r0 & (T_ - 1)) > 0) pv0 = *(const float2*)(xsrc + xi0 - D_);
                if ((r1 & (T_ - 1)) > 0) pv1 = *(const float2*)(xsrc + xi1 - D_);
                float g;
                float o0x, o0y, o1x, o1y;
                g = 1.f / (1.f + __expf(-v0.x)); o0x = (1.f - g) * xv0.x + g * pv0.x;
                g = 1.f / (1.f + __expf(-v0.y)); o0y = (1.f - g) * xv0.y + g * pv0.y;
                g = 1.f / (1.f + __expf(-v1.x)); o1x = (1.f - g) * xv1.x + g * pv1.x;
                g = 1.f / (1.f + __expf(-v1.y)); o1y = (1.f - g) * xv1.y + g * pv1.y;
                *(float2*)(C + xi0) = make_float2(o0x, o0y);
                *(float2*)(C + xi1) = make_float2(o1x, o1y);
                __nv_bfloat162 h0, h1, l0, l1;
                h0.x = __float2bfloat16(o0x); h0.y = __float2bfloat16(o0y);
                h1.x = __float2bfloat16(o1x); h1.y = __float2bfloat16(o1y);
                l0.x = __float2bfloat16(o0x - __bfloat162float(h0.x));
                l0.y = __float2bfloat16(o0y - __bfloat162float(h0.y));
                l1.x = __float2bfloat16(o1x - __bfloat162float(h1.x));
                l1.y = __float2bfloat16(o1y - __bfloat162float(h1.y));
                *(__nv_bfloat162*)(bh16 + xi0) = h0;
                *(__nv_bfloat162*)(bh16 + xi1) = h1;
                *(__nv_bfloat162*)(bl16 + xi0) = l0;
                *(__nv_bfloat162*)(bl16 + xi1) = l1;
            } else if (mode & 16) {
                __half* Ch = (__half*)C;
                const int cH = c0 >> 1;
                float a0 = v0.x / (1.f + __expf(-v0.x)) * v0.y;
                float a1 = v1.x / (1.f + __expf(-v1.x)) * v1.y;
                Ch[(size_t)r0 * ldc + cH]       = __float2half(a0);
                Ch[(size_t)(r0 + 8) * ldc + cH] = __float2half(a1);
            } else {
                const size_t i0 = (size_t)r0 * ldc + c0;
                const size_t i1 = (size_t)(r0 + 8) * ldc + c0;
                if (mode & 2) {
                    float2 r0v = *(const float2*)(res + i0);
                    float2 r1v = *(const float2*)(res + i1);
                    v0.x += r0v.x; v0.y += r0v.y;
                    v1.x += r1v.x; v1.y += r1v.y;
                }
                if (mode & 4) {
                    __half* Ch = (__half*)C;
                    __half2 h0, h1;
                    h0.x = __float2half(v0.x); h0.y = __float2half(v0.y);
                    h1.x = __float2half(v1.x); h1.y = __float2half(v1.y);
                    *(__half2*)(Ch + i0) = h0;
                    *(__half2*)(Ch + i1) = h1;
                } else {
                    *(float2*)(C + i0) = v0;
                    *(float2*)(C + i1) = v1;
                }
            }
        }
    }
    #undef LOAD_BUFH
}

// ---------------------------------------------------------------------------
// bf16 3-term split GEMM (dd projection only)
// ---------------------------------------------------------------------------
__global__ __launch_bounds__(256, 1) void mma_gemm(
    const __nv_bfloat16* __restrict__ Ah, const __nv_bfloat16* __restrict__ Al,
    const __nv_bfloat16* __restrict__ Wh, const __nv_bfloat16* __restrict__ Wl,
    const float* __restrict__ bias,
    float* __restrict__ C, int K, int NKB, int ldc)
{
    extern __shared__ char smem[];
    const uint32_t su = smem_u32(smem);
    const int tid = threadIdx.x;
    const int wid = tid >> 5, lane = tid & 31;
    const int wm = wid >> 2, wn = wid & 3;
    const int m0 = blockIdx.y * 128, n0 = blockIdx.x * 128;

    const uint32_t a_lrow = (uint32_t)(wm * 64 + (lane & 15)) * 80u + ((lane >> 4) * 16u);
    const uint32_t b_lrow = (uint32_t)(wn * 32 + ((lane >> 4) & 1) * 8 + (lane & 7)) * 80u
                          + (((lane >> 3) & 1) * 16u);

    float acc[4][4][4] = {};

    const int ch0 = tid * 2;
    #define LOAD_BUF(kb, b) do {                                              \
        _Pragma("unroll")                                                     \
        for (int c = 0; c < 2; c++) {                                         \
            const int ch = ch0 + c;                                           \
            const int row = ch >> 2, sub = ch & 3;                            \
            const uint32_t dst = su + (b) * BUFB + (uint32_t)row * 80u + sub * 16u; \
            const size_t asrc = (size_t)(m0 + row) * K + (kb) * 32 + sub * 8; \
            const size_t wsrc = (size_t)(n0 + row) * K + (kb) * 32 + sub * 8; \
            CP_ASYNC16(dst +        0, Ah + asrc);                            \
            CP_ASYNC16(dst +     MATB, Al + asrc);                            \
            CP_ASYNC16(dst + 2 * MATB, Wh + wsrc);                            \
            CP_ASYNC16(dst + 3 * MATB, Wl + wsrc);                            \
        }                                                                     \
    } while (0)

    LOAD_BUF(0, 0);
    CP_COMMIT();
    LOAD_BUF(1, 1);
    CP_COMMIT();

    int stage = 0;
    for (int kb = 0; kb < NKB; kb++) {
        if (kb + 1 < NKB) { CP_WAIT1(); } else { CP_WAIT0(); }
        __syncthreads();
        if (kb + 2 < NKB) {
            int ns = stage + 2; if (ns >= 3) ns -= 3;
            LOAD_BUF(kb + 2, ns);
            CP_COMMIT();
        }

        const uint32_t sb = su + stage * BUFB;
        #pragma unroll
        for (int ks = 0; ks < 2; ks++) {
            uint32_t ah[4][4], al[4][4];
            uint32_t bh[2][4], bl[2][4];
            #pragma unroll
            for (int mt = 0; mt < 4; mt++) {
                const uint32_t ra = sb + a_lrow + (uint32_t)mt * 16u * 80u + ks * 32u;
                LDSM_X4(ah[mt][0], ah[mt][1], ah[mt][2], ah[mt][3], ra);
                LDSM_X4(al[mt][0], al[mt][1], al[mt][2], al[mt][3], ra + MATB);
            }
            #pragma unroll
            for (int np = 0; np < 2; np++) {
                const uint32_t rb = sb + 2 * MATB + b_lrow + (uint32_t)np * 16u * 80u + ks * 32u;
                LDSM_X4(bh[np][0], bh[np][1], bh[np][2], bh[np][3], rb);
                LDSM_X4(bl[np][0], bl[np][1], bl[np][2], bl[np][3], rb + MATB);
            }
            #pragma unroll
            for (int mt = 0; mt < 4; mt++)
                #pragma unroll
                for (int nt = 0; nt < 4; nt++) {
                    const int np = nt >> 1, o = (nt & 1) * 2;
                    MMA16816(acc[mt][nt], ah[mt], bh[np][o], bh[np][o + 1]);
                    MMA16816(acc[mt][nt], ah[mt], bl[np][o], bl[np][o + 1]);
                    MMA16816(acc[mt][nt], al[mt], bh[np][o], bh[np][o + 1]);
                }
        }
        stage++; if (stage >= 3) stage = 0;
    }

    const int qrow = lane >> 2, qcol = (lane & 3) * 2;
    #pragma unroll
    for (int mt = 0; mt < 4; mt++) {
        const int r0 = m0 + wm * 64 + mt * 16 + qrow;
        #pragma unroll
        for (int nt = 0; nt < 4; nt++) {
            const int c0 = n0 + wn * 32 + nt * 8 + qcol;
            float bx = bias[c0], by = bias[c0 + 1];
            *(float2*)(C + (size_t)r0 * ldc + c0) =
                make_float2(acc[mt][nt][0] + bx, acc[mt][nt][1] + by);
            *(float2*)(C + (size_t)(r0 + 8) * ldc + c0) =
                make_float2(acc[mt][nt][2] + bx, acc[mt][nt][3] + by);
        }
    }
    #undef LOAD_BUF
}

// ---------------------------------------------------------------------------
// RMSNorm -> single fp16 output
// ---------------------------------------------------------------------------
__global__ __launch_bounds__(256) void rmsnorm_half_kernel(
    const float* __restrict__ x, const float* __restrict__ w,
    __half* __restrict__ oh)
{
    const int row = blockIdx.x;
    const int tid = threadIdx.x;
    const float* xr = x + (size_t)row * D_;
    float4 v = *(const float4*)(xr + tid * 4);
    float s = v.x * v.x + v.y * v.y + v.z * v.z + v.w * v.w;
    #pragma unroll
    for (int m = 16; m > 0; m >>= 1) s += __shfl_xor_sync(0xffffffffu, s, m);
    __shared__ float red[8];
    if ((tid & 31) == 0) red[tid >> 5] = s;
    __syncthreads();
    if (tid < 32) {
        float t = (tid < 8) ? red[tid] : 0.f;
        #pragma unroll
        for (int m = 4; m > 0; m >>= 1) t += __shfl_xor_sync(0xffffffffu, t, m);
        if (tid == 0) red[0] = t;
    }
    __syncthreads();
    const float inv = rsqrtf(red[0] / (float)D_ + EPS_);
    float4 wv = *(const float4*)(w + tid * 4);
    __half hb[4] = { __float2half(v.x * inv * wv.x), __float2half(v.y * inv * wv.y),
                     __float2half(v.z * inv * wv.z), __float2half(v.w * inv * wv.w) };
    *(uint2*)(oh + (size_t)row * D_ + tid * 4) = *(uint2*)hb;
}

// ---------------------------------------------------------------------------
// 3-phase cumsum
// ---------------------------------------------------------------------------
__global__ void cumsumA(const float* __restrict__ dd, float* __restrict__ cs)
{
    const int c = threadIdx.x;
    const int blk = blockIdx.x;
    const int b = blk >> 4, ch = blk & 15;
    size_t base = ((size_t)b * T_ + ch * 128) * 256 + c;
    float s = 0.f;
    #pragma unroll 8
    for (int t = 0; t < 128; t++) { s += dd[base]; base += 256; }
    cs[(size_t)blk * 256 + c] = s;
}
__global__ void cumsumB(float* __restrict__ cs)
{
    const int c = threadIdx.x;
    const int b = blockIdx.x;
    float run = 0.f;
    #pragma unroll
    for (int ch = 0; ch < 16; ch++) {
        size_t i = ((size_t)b * 16 + ch) * 256 + c;
        float t = cs[i];
        cs[i] = run;
        run += t;
    }
}
__global__ void cumsumC(float* __restrict__ dd, const float* __restrict__ cs)
{
    const int c = threadIdx.x;
    const int blk = blockIdx.x;
    const int b = blk >> 4, ch = blk & 15;
    float acc = cs[(size_t)blk * 256 + c];
    size_t base = ((size_t)b * T_ + ch * 128) * 256 + c;
    #pragma unroll 8
    for (int t = 0; t < 128; t++) { acc += dd[base]; dd[base] = acc; base += 256; }
}

// ---------------------------------------------------------------------------
// q/k head rmsnorm + hybrid rope + head-major scatter (fp16 in/out)
// ---------------------------------------------------------------------------
__global__ __launch_bounds__(256) void qkv_transform_h(
    const __half* __restrict__ qkv, const float* __restrict__ ddcum,
    const float* __restrict__ rc, const float* __restrict__ rs,
    const float* __restrict__ qnw, const float* __restrict__ knw,
    const float* __restrict__ qpb, const float* __restrict__ kpb,
    __half* __restrict__ qt, __half* __restrict__ kt, __half* __restrict__ vt)
{
    const int w = blockIdx.x * 8 + (threadIdx.x >> 5);
    const int lane = threadIdx.x & 31;
    const int b = w >> 15;
    const int rem = w & 32767;
    const int t = rem >> 4;
    const int h = rem & 15;

    const size_t base = ((size_t)(b * T_ + t) * 3) * D_ + h * DH_;
    float q0 = __half2float(qkv[base + lane]);
    float q1 = __half2float(qkv[base + 32 + lane]);
    float k0 = __half2float(qkv[base + D_ + lane]);
    float k1 = __half2float(qkv[base + D_ + 32 + lane]);
    __half v0 = qkv[base + 2 * D_ + lane];
    __half v1 = qkv[base + 2 * D_ + 32 + lane];

    float sq = q0 * q0 + q1 * q1;
    float sk = k0 * k0 + k1 * k1;
    #pragma unroll
    for (int m = 16; m > 0; m >>= 1) {
        sq += __shfl_xor_sync(0xffffffffu, sq, m);
        sk += __shfl_xor_sync(0xffffffffu, sk, m);
    }
    const float rq = rsqrtf(sq / 64.f + EPS_);
    const float rk = rsqrtf(sk / 64.f + EPS_);
    q0 *= rq * qnw[lane] * qpb[lane];
    q1 *= rq * qnw[lane + 32] * qpb[lane + 32];
    k0 *= rk * knw[lane] * kpb[lane];
    k1 *= rk * knw[lane + 32] * kpb[lane + 32];

    const int j = lane & 15;
    const float c = rc[t * 32 + j], s = rs[t * 32 + j];
    const float ang = ddcum[((size_t)(b * T_ + t)) * 256 + h * 16 + j];
    float s2, c2;
    sincosf(ang, &s2, &c2);

    const float qp0 = __shfl_xor_sync(0xffffffffu, q0, 16);
    const float qp1 = __shfl_xor_sync(0xffffffffu, q1, 16);
    const float kp0 = __shfl_xor_sync(0xffffffffu, k0, 16);
    const float kp1 = __shfl_xor_sync(0xffffffffu, k1, 16);
    float oq0, oq1, ok0, ok1;
    if (lane < 16) {
        oq0 = q0 * c - qp0 * s;  oq1 = q1 * c2 - qp1 * s2;
        ok0 = k0 * c - kp0 * s;  ok1 = k1 * c2 - kp1 * s2;
    } else {
        oq0 = q0 * c + qp0 * s;  oq1 = q1 * c2 + qp1 * s2;
        ok0 = k0 * c + kp0 * s;  ok1 = k1 * c2 + kp1 * s2;
    }

    const size_t ob = ((size_t)(b * NH_ + h) * T_ + t) * DH_;
    qt[ob + lane]      = __float2half(oq0 * 0.125f);
    qt[ob + 32 + lane] = __float2half(oq1 * 0.125f);
    kt[ob + lane]      = __float2half(ok0);
    kt[ob + 32 + lane] = __float2half(ok1);
    vt[ob + lane]      = v0;
    vt[ob + 32 + lane] = v1;
}

// ---------------------------------------------------------------------------
// fp16 flash attention (register-resident P), 2 CTAs/SM
// ---------------------------------------------------------------------------
#define FSMEMH (64 * 72 * 2 + 32 * 72 * 4)

__global__ __launch_bounds__(256, 2) void flash_h(
    const __half* __restrict__ qt, const __half* __restrict__ kt,
    const __half* __restrict__ vt, __half* __restrict__ yh)
{
    extern __shared__ __half fsmh[];
    __half* Ks = fsmh;
    uint32_t* Vs2 = (uint32_t*)(fsmh + 64 * 72);

    const int tid = threadIdx.x, lane = tid & 31, w = tid >> 5;
    const int bx = gridDim.x - 1 - blockIdx.x;
    const int bh = blockIdx.y;
    const int b = bh >> 4, h = bh & 15;
    const int m0 = bx * 128;

    const __half* Qb = qt + (size_t)bh * T_ * DH_;
    const __half* Kb = kt + (size_t)bh * T_ * DH_;
    const __half* Vb = vt + (size_t)bh * T_ * DH_;

    const int r1 = m0 + w * 16 + (lane >> 2);
    uint32_t qf[4][4];
    {
        const __half* q1 = Qb + (size_t)r1 * DH_;
        const __half* q2 = q1 + 8 * DH_;
        #pragma unroll
        for (int c = 0; c < 4; c++) {
            const int col = c * 16 + 2 * (lane & 3);
            qf[c][0] = *(const uint32_t*)(q1 + col);
            qf[c][1] = *(const uint32_t*)(q2 + col);
            qf[c][2] = *(const uint32_t*)(q1 + col + 8);
            qf[c][3] = *(const uint32_t*)(q2 + col + 8);
        }
    }

    float mi[2] = { -1e30f, -1e30f }, li[2] = { 0.f, 0.f };
    float O[8][4] = {};

    const int ntiles = 2 * bx + 2;
    for (int nt = 0; nt < ntiles; nt++) {
        const int n0 = nt * 64;
        __syncthreads();
        {
            const int key = tid >> 2, db = (tid & 3) * 16;
            const __half* kp = Kb + (size_t)(n0 + key) * DH_ + db;
            *(uint4*)&Ks[key * 72 + db]     = *(const uint4*)kp;
            *(uint4*)&Ks[key * 72 + db + 8] = *(const uint4*)(kp + 8);
            const int kp2 = tid >> 3, dv = (tid & 7) * 8;
            const __half* v0p = Vb + (size_t)(n0 + 2 * kp2) * DH_ + dv;
            const __half* v1p = v0p + DH_;
            __half a8[8], b8[8];
            *(uint4*)a8 = *(const uint4*)v0p;
            *(uint4*)b8 = *(const uint4*)v1p;
            uint32_t pk[8];
            #pragma unroll
            for (int i = 0; i < 8; i++) {
                __half2 t2; t2.x = a8[i]; t2.y = b8[i];
                pk[i] = *(uint32_t*)&t2;
            }
            *(uint4*)&Vs2[kp2 * 72 + dv]     = *(uint4*)pk;
            *(uint4*)&Vs2[kp2 * 72 + dv + 4] = *(uint4*)(pk + 4);
        }
        __syncthreads();

        float S[8][4] = {};
        #pragma unroll
        for (int c = 0; c < 4; c++) {
            #pragma unroll
            for (int n8 = 0; n8 < 8; n8++) {
                const __half* kr = &Ks[(n8 * 8 + (lane >> 2)) * 72 + c * 16 + 2 * (lane & 3)];
                uint32_t b0 = *(const uint32_t*)kr;
                uint32_t b1 = *(const uint32_t*)(kr + 8);
                MMAH16816(S[n8], qf[c], b0, b1);
            }
        }
        if (nt >= 2 * bx) {
            #pragma unroll
            for (int n8 = 0; n8 < 8; n8++) {
                const int cb = n0 + n8 * 8 + 2 * (lane & 3);
                if (cb     > r1)     S[n8][0] = -1e30f;
                if (cb + 1 > r1)     S[n8][1] = -1e30f;
                if (cb     > r1 + 8) S[n8][2] = -1e30f;
                if (cb + 1 > r1 + 8) S[n8][3] = -1e30f;
            }
        }
        #pragma unroll
        for (int half = 0; half < 2; half++) {
            float mx = -1e30f;
            #pragma unroll
            for (int n8 = 0; n8 < 8; n8++)
                mx = fmaxf(mx, fmaxf(S[n8][half * 2], S[n8][half * 2 + 1]));
            mx = fmaxf(mx, __shfl_xor_sync(0xffffffffu, mx, 1));
            mx = fmaxf(mx, __shfl_xor_sync(0xffffffffu, mx, 2));
            const float mnew = fmaxf(mi[half], mx);
            const float corr = __expf(mi[half] - mnew);
            float rsum = 0.f;
            #pragma unroll
            for (int n8 = 0; n8 < 8; n8++) {
                float e0 = __expf(S[n8][half * 2]     - mnew);
                float e1 = __expf(S[n8][half * 2 + 1] - mnew);
                S[n8][half * 2] = e0; S[n8][half * 2 + 1] = e1;
                rsum += e0 + e1;
            }
            rsum += __shfl_xor_sync(0xffffffffu, rsum, 1);
            rsum += __shfl_xor_sync(0xffffffffu, rsum, 2);
            li[half] = li[half] * corr + rsum;
            mi[half] = mnew;
            #pragma unroll
            for (int n8 = 0; n8 < 8; n8++) {
                O[n8][half * 2]     *= corr;
                O[n8][half * 2 + 1] *= corr;
            }
        }
        #pragma unroll
        for (int c = 0; c < 4; c++) {
            uint32_t a[4];
            a[0] = h2bits(S[2 * c][0],     S[2 * c][1]);
            a[1] = h2bits(S[2 * c][2],     S[2 * c][3]);
            a[2] = h2bits(S[2 * c + 1][0], S[2 * c + 1][1]);
            a[3] = h2bits(S[2 * c + 1][2], S[2 * c + 1][3]);
            const uint32_t* vr0 = &Vs2[((lane & 3) + c * 8) * 72 + (lane >> 2)];
            const uint32_t* vr1 = vr0 + 4 * 72;
            #pragma unroll
            for (int n8 = 0; n8 < 8; n8++) {
                MMAH16816(O[n8], a, vr0[n8 * 8], vr1[n8 * 8]);
            }
        }
    }

    const float inv0 = 1.f / li[0], inv1 = 1.f / li[1];
    const size_t o1 = ((size_t)(b * T_ + r1)) * D_ + h * DH_ + 2 * (lane & 3);
    const size_t o2 = o1 + 8 * D_;
    #pragma unroll
    for (int n8 = 0; n8 < 8; n8++) {
        __half2 h0, h1;
        h0.x = __float2half(O[n8][0] * inv0); h0.y = __float2half(O[n8][1] * inv0);
        h1.x = __float2half(O[n8][2] * inv1); h1.y = __float2half(O[n8][3] * inv1);
        *(__half2*)(yh + o1 + n8 * 8) = h0;
        *(__half2*)(yh + o2 + n8 * 8) = h1;
    }
}

// ---------------------------------------------------------------------------
// Launch (two-stream fork/join inside graph capture)
// ---------------------------------------------------------------------------
static inline int cdiv(long long a, long long b) { return (int)((a + b - 1) / b); }

extern "C" void kernel_launch(void* const* d_in, const int* in_sizes, int n_in,
                              void* d_out, int out_size)
{
    const float* x     = (const float*)d_in[0];
    const float* rc    = (const float*)d_in[1];
    const float* rs    = (const float*)d_in[2];
    const float* lerpw = (const float*)d_in[3];
    const float* lerpb = (const float*)d_in[4];
    const float* anw   = (const float*)d_in[5];
    const float* wqkv  = (const float*)d_in[6];
    const float* qnw   = (const float*)d_in[7];
    const float* knw   = (const float*)d_in[8];
    const float* qpb   = (const float*)d_in[9];
    const float* kpb   = (const float*)d_in[10];
    const float* ddw   = (const float*)d_in[11];
    const float* ddb   = (const float*)d_in[12];
    const float* wo    = (const float*)d_in[13];
    const float* mnw   = (const float*)d_in[14];
    const float* gw    = (const float*)d_in[15];
    const float* uw    = (const float*)d_in[16];
    const float* dw    = (const float*)d_in[17];
    float* out = (float*)d_out;

    float *xmix, *dd, *cs, *x2;
    __half *qkvh, *qth, *kth, *vth, *guh;
    __nv_bfloat16 *ah, *al, *wh, *wl;
    __half *af, *wf;
    cudaGetSymbolAddress((void**)&xmix, s_xmix);
    cudaGetSymbolAddress((void**)&dd,   s_dd);
    cudaGetSymbolAddress((void**)&cs,   s_csum);
    cudaGetSymbolAddress((void**)&x2,   s_x2);
    cudaGetSymbolAddress((void**)&qkvh, s_qkvh);
    cudaGetSymbolAddress((void**)&qth,  s_qth);
    cudaGetSymbolAddress((void**)&kth,  s_kth);
    cudaGetSymbolAddress((void**)&vth,  s_vth);
    cudaGetSymbolAddress((void**)&guh,  s_guh);
    cudaGetSymbolAddress((void**)&ah,   g_ah);
    cudaGetSymbolAddress((void**)&al,   g_al);
    cudaGetSymbolAddress((void**)&wh,   g_wh);
    cudaGetSymbolAddress((void**)&wl,   g_wl);
    cudaGetSymbolAddress((void**)&af,   g_af);
    cudaGetSymbolAddress((void**)&wf,   g_wf);

    cudaFuncSetAttribute(mma_gemm,
                         cudaFuncAttributeMaxDynamicSharedMemorySize, 3 * BUFB);
    cudaFuncSetAttribute(mma_gemm_h,
                         cudaFuncAttributeMaxDynamicSharedMemorySize, 3 * BUFBH);
    cudaFuncSetAttribute(flash_h,
                         cudaFuncAttributeMaxDynamicSharedMemorySize, FSMEMH);

    const dim3 blk(256);
    const int GSM  = 3 * BUFB;
    const int GSMH = 3 * BUFBH;
    cudaStream_t s0 = 0, s2 = g_ss.s2;

    // ---- stream 0: x conversion + fused lerp/mix GEMM ----
    conv_half<<<(M_ * D_ / 4) / 256, blk, 0, s0>>>(x, af);
    conv_whalf<<<cdiv((long long)D_ * D_, 256), blk, 0, s0>>>(lerpw, wf + WF0, D_, D_, D_, D_);
    mma_gemm_h<<<dim3(8, 32), blk, GSMH, s0>>>(af, wf + WF0, lerpb, nullptr, xmix,
                                               x, ah, al, D_, 32, D_, 1 | 8);
    cudaEventRecord(g_ss.evA, s0);

    // ---- stream 2: dd chain + gu/dw weight conversions ----
    convsplit<<<cdiv(256LL * D_, 256), blk, 0, s2>>>(ddw, wh, wl, 256, D_, 256, D_);
    cudaStreamWaitEvent(s2, g_ss.evA, 0);
    mma_gemm<<<dim3(2, 32), blk, GSM, s2>>>(ah, al, wh, wl, ddb, dd, D_, 32, 256);
    cumsumA<<<B_ * 16, blk, 0, s2>>>(dd, cs);
    cumsumB<<<B_, blk, 0, s2>>>(cs);
    cumsumC<<<B_ * 16, blk, 0, s2>>>(dd, cs);
    cudaEventRecord(g_ss.evB1, s2);
    conv_wgu<<<cdiv((long long)2 * FFNP * D_, 256), blk, 0, s2>>>(gw, uw, wf + WFGU);
    conv_whalf<<<cdiv((long long)D_ * FFNP, 256), blk, 0, s2>>>(dw, wf + WFDW,
                                                                D_, FFN_, D_, FFNP);
    cudaEventRecord(g_ss.evB2, s2);

    // ---- stream 0: main path ----
    rmsnorm_half_kernel<<<M_, blk, 0, s0>>>(xmix, anw, af);
    conv_whalf<<<cdiv((long long)3 * D_ * D_, 256), blk, 0, s0>>>(wqkv, wf + WF0,
                                                                  3 * D_, D_, 3 * D_, D_);
    mma_gemm_h<<<dim3(24, 32), blk, GSMH, s0>>>(af, wf + WF0, nullptr, nullptr,
                                                (float*)qkvh, nullptr, nullptr, nullptr,
                                                D_, 32, 3 * D_, 4);
    cudaStreamWaitEvent(s0, g_ss.evB1, 0);
    qkv_transform_h<<<(B_ * T_ * NH_) / 8, blk, 0, s0>>>(qkvh, dd, rc, rs, qnw, knw,
                                                         qpb, kpb, qth, kth, vth);
    flash_h<<<dim3(T_ / 128, B_ * NH_), blk, FSMEMH, s0>>>(qth, kth, vth, af);
    conv_whalf<<<cdiv((long long)D_ * D_, 256), blk, 0, s0>>>(wo, wf + WF0, D_, D_, D_, D_);
    mma_gemm_h<<<dim3(8, 32), blk, GSMH, s0>>>(af, wf + WF0, nullptr, xmix, x2,
                                               nullptr, nullptr, nullptr, D_, 32, D_, 2);
    rmsnorm_half_kernel<<<M_, blk, 0, s0>>>(x2, mnw, af);
    cudaStreamWaitEvent(s0, g_ss.evB2, 0);
    mma_gemm_h<<<dim3(44, 32), blk, GSMH, s0>>>(af, wf + WFGU, nullptr, nullptr,
                                                (float*)guh, nullptr, nullptr, nullptr,
                                                D_, 32, FFNP, 16);
    mma_gemm_h<<<dim3(8, 32), blk, GSMH, s0>>>(guh, wf + WFDW, nullptr, x2, out,
                                               nullptr, nullptr, nullptr, FFNP, 88, D_, 2);
}